// round 4
// baseline (speedup 1.0000x reference)
#include <cuda_runtime.h>
#include <cstdint>

#define D_MODEL   2048
#define HIDDEN    2048
#define NUM_HEADS 16
#define HEAD_DIM  128
#define BATCH     4
#define SEQ       2048
#define MROWS     (BATCH*SEQ)      // 8192
#define GK        2048
#define GN        2048

// ---------------- scratch (device globals; no allocation allowed) ----------
__device__ float g_q[(size_t)MROWS * HIDDEN];   // [B,H,S,hd]
__device__ float g_k[(size_t)MROWS * HIDDEN];   // [B,H,S,hd]
__device__ float g_v[(size_t)MROWS * HIDDEN];   // [B,H,S,hd]
__device__ float g_ao[(size_t)MROWS * HIDDEN];  // [B,S,H*hd] = [M, 2048]

// ---------------- GEMM: C = A @ W + bias, M=8192 N=2048 K=2048 -------------
// MODE 0: Q proj -> RoPE -> g_q (headed layout)
// MODE 1: K proj -> RoPE -> g_k
// MODE 2: V proj ->        g_v
// MODE 3: O proj: A = g_ao, write param out [M,N]
#define BM 128
#define BN 128
#define BK 16

template<int MODE>
__global__ __launch_bounds__(256) void gemm_kernel(
    const float* __restrict__ A, const float* __restrict__ W,
    const float* __restrict__ bias, float* __restrict__ out,
    const float* __restrict__ cosT, const float* __restrict__ sinT)
{
    __shared__ float As[2][BK][BM + 4];
    __shared__ float Bs[2][BK][BN];

    const int tid = threadIdx.x;
    const int m0 = blockIdx.y * BM;
    const int n0 = blockIdx.x * BN;
    const float* Ap = (MODE == 3) ? g_ao : A;

    const int r0 = (tid >> 4) << 3;   // 8 rows per thread
    const int c0 = (tid & 15) << 3;   // 8 cols per thread

    float acc[8][8];
#pragma unroll
    for (int i = 0; i < 8; i++)
#pragma unroll
        for (int j = 0; j < 8; j++) acc[i][j] = 0.f;

    int a_row[2], a_k[2], b_row[2], b_col[2];
#pragma unroll
    for (int j = 0; j < 2; j++) {
        int lin = tid + j * 256;
        a_row[j] = lin >> 2;  a_k[j] = (lin & 3) << 2;
        b_row[j] = lin >> 5;  b_col[j] = (lin & 31) << 2;
    }

    float4 pa[2], pb[2];
    // prologue: tile 0
#pragma unroll
    for (int j = 0; j < 2; j++) {
        pa[j] = *(const float4*)&Ap[(size_t)(m0 + a_row[j]) * GK + a_k[j]];
        pb[j] = *(const float4*)&W[(size_t)b_row[j] * GN + n0 + b_col[j]];
    }
#pragma unroll
    for (int j = 0; j < 2; j++) {
        As[0][a_k[j] + 0][a_row[j]] = pa[j].x;
        As[0][a_k[j] + 1][a_row[j]] = pa[j].y;
        As[0][a_k[j] + 2][a_row[j]] = pa[j].z;
        As[0][a_k[j] + 3][a_row[j]] = pa[j].w;
        *(float4*)&Bs[0][b_row[j]][b_col[j]] = pb[j];
    }
    __syncthreads();

    const int NT = GK / BK;  // 128
    for (int kt = 0; kt < NT; kt++) {
        const int cur = kt & 1;
        if (kt + 1 < NT) {
#pragma unroll
            for (int j = 0; j < 2; j++) {
                pa[j] = *(const float4*)&Ap[(size_t)(m0 + a_row[j]) * GK + (kt + 1) * BK + a_k[j]];
                pb[j] = *(const float4*)&W[(size_t)((kt + 1) * BK + b_row[j]) * GN + n0 + b_col[j]];
            }
        }
#pragma unroll
        for (int kk = 0; kk < BK; kk++) {
            float a[8], b[8];
            *(float4*)&a[0] = *(const float4*)&As[cur][kk][r0];
            *(float4*)&a[4] = *(const float4*)&As[cur][kk][r0 + 4];
            *(float4*)&b[0] = *(const float4*)&Bs[cur][kk][c0];
            *(float4*)&b[4] = *(const float4*)&Bs[cur][kk][c0 + 4];
#pragma unroll
            for (int i = 0; i < 8; i++)
#pragma unroll
                for (int j = 0; j < 8; j++)
                    acc[i][j] += a[i] * b[j];
        }
        if (kt + 1 < NT) {
            const int nxt = cur ^ 1;
#pragma unroll
            for (int j = 0; j < 2; j++) {
                As[nxt][a_k[j] + 0][a_row[j]] = pa[j].x;
                As[nxt][a_k[j] + 1][a_row[j]] = pa[j].y;
                As[nxt][a_k[j] + 2][a_row[j]] = pa[j].z;
                As[nxt][a_k[j] + 3][a_row[j]] = pa[j].w;
                *(float4*)&Bs[nxt][b_row[j]][b_col[j]] = pb[j];
            }
        }
        __syncthreads();
    }

    // ---- epilogue ----
    float bv[8];
    *(float4*)&bv[0] = *(const float4*)&bias[n0 + c0];
    *(float4*)&bv[4] = *(const float4*)&bias[n0 + c0 + 4];

#pragma unroll
    for (int i = 0; i < 8; i++) {
        const int m = m0 + r0 + i;
        float v[8];
#pragma unroll
        for (int j = 0; j < 8; j++) v[j] = acc[i][j] + bv[j];

        if (MODE == 3) {
            *(float4*)&out[(size_t)m * GN + n0 + c0]     = make_float4(v[0], v[1], v[2], v[3]);
            *(float4*)&out[(size_t)m * GN + n0 + c0 + 4] = make_float4(v[4], v[5], v[6], v[7]);
        } else {
            const int bb = m >> 11;          // m / SEQ
            const int s  = m & 2047;         // m % SEQ
            const int hh = (n0 + c0) >> 7;   // head
            const int d0 = (n0 + c0) & 127;  // dim within head (multiple of 8)
            float w[8];
            if (MODE <= 1) {
                const int i0 = d0 >> 1;      // pair index base
#pragma unroll
                for (int p = 0; p < 4; p++) {
                    float cv = cosT[s * (HEAD_DIM / 2) + i0 + p];
                    float sv = sinT[s * (HEAD_DIM / 2) + i0 + p];
                    w[2 * p]     = v[2 * p] * cv - v[2 * p + 1] * sv;
                    w[2 * p + 1] = v[2 * p] * sv + v[2 * p + 1] * cv;
                }
            } else {
#pragma unroll
                for (int j = 0; j < 8; j++) w[j] = v[j];
            }
            float* dst = (MODE == 0) ? g_q : (MODE == 1) ? g_k : g_v;
            size_t o = ((size_t)(bb * NUM_HEADS + hh) * SEQ + s) * HEAD_DIM + d0;
            *(float4*)&dst[o]     = make_float4(w[0], w[1], w[2], w[3]);
            *(float4*)&dst[o + 4] = make_float4(w[4], w[5], w[6], w[7]);
        }
    }
}

// ---------------- flash attention (causal), fp32 ---------------------------
// Block: one (b, h, 64-query tile). 256 threads.
// SMEM float layout (padded strides chosen for <=2-way conflicts):
//   Qs [64][128]  @0
//   Ks [64][132]  @8192
//   Vs [64][128]  @16640
//   Ss [64][68]   @24832
//   rowm/rowl/rowa [64] each @29184/29248/29312  -> total 29376 floats
#define ATTN_SMEM_FLOATS 29376
#define ATTN_SMEM_BYTES  (ATTN_SMEM_FLOATS * 4)

__global__ __launch_bounds__(256, 1) void attn_kernel()
{
    extern __shared__ float sm[];
    float* Qs   = sm;
    float* Ks   = sm + 8192;
    float* Vs   = sm + 16640;
    float* Ss   = sm + 24832;
    float* rowm = sm + 29184;
    float* rowl = sm + 29248;
    float* rowa = sm + 29312;

    const int tid = threadIdx.x;
    const int qt = blockIdx.x, h = blockIdx.y, b = blockIdx.z;
    const int q0 = qt * 64;
    const size_t base = ((size_t)(b * NUM_HEADS + h)) * SEQ * HEAD_DIM;
    const float scale = 0.088388347648318447f;  // 1/sqrt(128)

    // load Q tile, pre-scaled
    for (int idx = tid; idx < 2048; idx += 256) {
        int r = idx >> 5, c4 = (idx & 31) << 2;
        float4 v = *(const float4*)&g_q[base + (size_t)(q0 + r) * HEAD_DIM + c4];
        v.x *= scale; v.y *= scale; v.z *= scale; v.w *= scale;
        *(float4*)&Qs[r * 128 + c4] = v;
    }
    if (tid < 64) { rowm[tid] = -1e30f; rowl[tid] = 0.f; }

    const int org = tid >> 5;   // O rows: org*8 .. +8
    const int ocg = tid & 31;   // O cols: ocg*4 .. +4
    const int srg = tid >> 4;   // S rows: srg*4 .. +4
    const int scg = tid & 15;   // S kcols: {scg, scg+16, scg+32, scg+48}

    float oacc[8][4];
#pragma unroll
    for (int i = 0; i < 8; i++)
#pragma unroll
        for (int u = 0; u < 4; u++) oacc[i][u] = 0.f;

    for (int t = 0; t <= qt; t++) {
        const int kv0 = t * 64;
        __syncthreads();  // prev tile's O-compute finished (Vs/Ss free)
        for (int idx = tid; idx < 2048; idx += 256) {
            int r = idx >> 5, c4 = (idx & 31) << 2;
            *(float4*)&Ks[r * 132 + c4] =
                *(const float4*)&g_k[base + (size_t)(kv0 + r) * HEAD_DIM + c4];
            *(float4*)&Vs[r * 128 + c4] =
                *(const float4*)&g_v[base + (size_t)(kv0 + r) * HEAD_DIM + c4];
        }
        __syncthreads();  // K/V tiles ready

        // ---- S = Q @ K^T (scaled), 4x4 micro-tile per thread ----
        float sacc[4][4];
#pragma unroll
        for (int i = 0; i < 4; i++)
#pragma unroll
            for (int j = 0; j < 4; j++) sacc[i][j] = 0.f;

#pragma unroll 8
        for (int c = 0; c < 128; c += 4) {
            float4 q4[4], k4[4];
#pragma unroll
            for (int i = 0; i < 4; i++)
                q4[i] = *(const float4*)&Qs[(srg * 4 + i) * 128 + c];
#pragma unroll
            for (int j = 0; j < 4; j++)
                k4[j] = *(const float4*)&Ks[(scg + 16 * j) * 132 + c];
#pragma unroll
            for (int i = 0; i < 4; i++)
#pragma unroll
                for (int j = 0; j < 4; j++)
                    sacc[i][j] += q4[i].x * k4[j].x + q4[i].y * k4[j].y +
                                  q4[i].z * k4[j].z + q4[i].w * k4[j].w;
        }
#pragma unroll
        for (int i = 0; i < 4; i++) {
            const int qg = q0 + srg * 4 + i;
#pragma unroll
            for (int j = 0; j < 4; j++) {
                const int kg = kv0 + scg + 16 * j;
                Ss[(srg * 4 + i) * 68 + scg + 16 * j] =
                    (kg <= qg) ? sacc[i][j] : -1e30f;
            }
        }
        __syncthreads();  // scores ready

        // ---- online softmax: one owner thread per row ----
        if (tid < 64) {
            float* srow = &Ss[tid * 68];
            float mold = rowm[tid];
            float mx = mold;
#pragma unroll 8
            for (int j = 0; j < 64; j++) mx = fmaxf(mx, srow[j]);
            float l = 0.f;
#pragma unroll 8
            for (int j = 0; j < 64; j++) {
                float p = __expf(srow[j] - mx);
                srow[j] = p;
                l += p;
            }
            float alpha = __expf(mold - mx);
            rowa[tid] = alpha;
            rowl[tid] = rowl[tid] * alpha + l;
            rowm[tid] = mx;
        }
        __syncthreads();  // P and alpha ready

        // ---- O = alpha*O + P @ V, 8x4 micro-tile per thread ----
#pragma unroll
        for (int i = 0; i < 8; i++) {
            float a = rowa[org * 8 + i];
#pragma unroll
            for (int u = 0; u < 4; u++) oacc[i][u] *= a;
        }
#pragma unroll 4
        for (int j = 0; j < 64; j += 4) {
            float4 v0 = *(const float4*)&Vs[(j + 0) * 128 + ocg * 4];
            float4 v1 = *(const float4*)&Vs[(j + 1) * 128 + ocg * 4];
            float4 v2 = *(const float4*)&Vs[(j + 2) * 128 + ocg * 4];
            float4 v3 = *(const float4*)&Vs[(j + 3) * 128 + ocg * 4];
#pragma unroll
            for (int i = 0; i < 8; i++) {
                float4 p = *(const float4*)&Ss[(org * 8 + i) * 68 + j];
                oacc[i][0] += p.x * v0.x + p.y * v1.x + p.z * v2.x + p.w * v3.x;
                oacc[i][1] += p.x * v0.y + p.y * v1.y + p.z * v2.y + p.w * v3.y;
                oacc[i][2] += p.x * v0.z + p.y * v1.z + p.z * v2.z + p.w * v3.z;
                oacc[i][3] += p.x * v0.w + p.y * v1.w + p.z * v2.w + p.w * v3.w;
            }
        }
    }

    // ---- normalize + write to [B,S,H*hd] ----
#pragma unroll
    for (int i = 0; i < 8; i++) {
        const int row = org * 8 + i;
        const float il = 1.0f / rowl[row];
        size_t o = ((size_t)(b * SEQ + q0 + row)) * HIDDEN + h * HEAD_DIM + ocg * 4;
        *(float4*)&g_ao[o] = make_float4(oacc[i][0] * il, oacc[i][1] * il,
                                         oacc[i][2] * il, oacc[i][3] * il);
    }
}

// ---------------- launch ---------------------------------------------------
extern "C" void kernel_launch(void* const* d_in, const int* in_sizes, int n_in,
                              void* d_out, int out_size)
{
    const float* x    = (const float*)d_in[0];
    const float* wq   = (const float*)d_in[1];
    const float* bq   = (const float*)d_in[2];
    const float* wk   = (const float*)d_in[3];
    const float* bk_  = (const float*)d_in[4];
    const float* wv   = (const float*)d_in[5];
    const float* bv   = (const float*)d_in[6];
    const float* wo   = (const float*)d_in[7];
    const float* bo   = (const float*)d_in[8];
    const float* cosT = (const float*)d_in[9];
    const float* sinT = (const float*)d_in[10];
    float* out = (float*)d_out;

    dim3 ggrid(GN / BN, MROWS / BM);  // (16, 64)

    gemm_kernel<0><<<ggrid, 256>>>(x, wq, bq, nullptr, cosT, sinT);
    gemm_kernel<1><<<ggrid, 256>>>(x, wk, bk_, nullptr, cosT, sinT);
    gemm_kernel<2><<<ggrid, 256>>>(x, wv, bv, nullptr, nullptr, nullptr);

    cudaFuncSetAttribute(attn_kernel,
                         cudaFuncAttributeMaxDynamicSharedMemorySize,
                         ATTN_SMEM_BYTES);
    attn_kernel<<<dim3(SEQ / 64, NUM_HEADS, BATCH), 256, ATTN_SMEM_BYTES>>>();

    gemm_kernel<3><<<ggrid, 256>>>(nullptr, wo, bo, out, nullptr, nullptr);
}